// round 10
// baseline (speedup 1.0000x reference)
#include <cuda_runtime.h>
#include <cuda_bf16.h>
#include <stdint.h>

// my_ceil(x) = sum_{k=1..150} sigmoid(100*(x-k)) + sigmoid(100*(x+k)) - 150
//
// R=100 => every term with |x-offset| >= 0.5 saturates EXACTLY in fp32; at
// most one term (offset rint(v), if in [-150,150]\{0}) is live. Ungated
// closed form (verified R3-R9, rel_err ~1.2e-7):
//
//   rc = clamp(rint(v), -150, 150)
//   f  = rc + min(|rc|,0.5) * (tanh(50*(v-rc)) - copysign(1, rc))
//
// R10: R7 operating point (evict_last 0.75 on x, evict_first stores, batched
// loads + compiler barrier) with UNROLL=6 and a GENEROUS 64-reg budget
// (__launch_bounds__(256,4)). R4/R9 proved reg squeezes (<=42) serialize the
// load batch; 64 regs holds 6 float4 buffers comfortably. 4 CTAs/SM x 8 warps
// x 6 loads = 192 in-flight LDG.128/SM vs R7's 160.

#define TPB 256
#define UNROLL 6

// ---- packed f32x2 helpers (sm_103a) ----
__device__ __forceinline__ unsigned long long pack2(float a, float b) {
    unsigned long long r;
    asm("mov.b64 %0, {%1,%2};" : "=l"(r) : "f"(a), "f"(b));
    return r;
}
__device__ __forceinline__ void unpack2(unsigned long long p, float& a, float& b) {
    asm("mov.b64 {%0,%1}, %2;" : "=f"(a), "=f"(b) : "l"(p));
}
__device__ __forceinline__ unsigned long long mul2(unsigned long long a, unsigned long long b) {
    unsigned long long r; asm("mul.rn.f32x2 %0, %1, %2;" : "=l"(r) : "l"(a), "l"(b)); return r;
}
__device__ __forceinline__ unsigned long long add2(unsigned long long a, unsigned long long b) {
    unsigned long long r; asm("add.rn.f32x2 %0, %1, %2;" : "=l"(r) : "l"(a), "l"(b)); return r;
}
__device__ __forceinline__ float tanh_fast(float x) {
    float r; asm("tanh.approx.f32 %0, %1;" : "=f"(r) : "f"(x)); return r;
}

// L2 eviction-policy loads/stores
__device__ __forceinline__ float4 ldg_keep(const float4* p, unsigned long long pol) {
    float4 v;
    asm volatile("ld.global.nc.L2::cache_hint.v4.f32 {%0,%1,%2,%3}, [%4], %5;"
                 : "=f"(v.x), "=f"(v.y), "=f"(v.z), "=f"(v.w)
                 : "l"(p), "l"(pol));
    return v;
}
__device__ __forceinline__ void stg_stream(float4* p, float4 v, unsigned long long pol) {
    asm volatile("st.global.L2::cache_hint.v4.f32 [%0], {%1,%2,%3,%4}, %5;"
                 :: "l"(p), "f"(v.x), "f"(v.y), "f"(v.z), "f"(v.w), "l"(pol)
                 : "memory");
}

#define CP   0x4B4000004B400000ull  //  12582912.0f (2^23+2^22, RNE magic)
#define CN   0xCB400000CB400000ull  // -12582912.0f
#define P50  0x4248000042480000ull  //  50.0f packed

__device__ __forceinline__ float finish(float r0, float v50) {
    float rc   = fminf(fmaxf(r0, -150.0f), 150.0f);               // 2x FMNMX
    float w    = fmaf(rc, -50.0f, v50);                           // FFMA
    float th   = tanh_fast(w);                                    // MUFU.TANH
    float smag = fminf(fabsf(rc), 0.5f);                          // FMNMX |src|
    float c1   = __uint_as_float(
        (__float_as_uint(rc) & 0x80000000u) | 0x3F800000u);       // LOP3
    return fmaf(smag, th - c1, rc);                               // FADD + FFMA
}

__device__ __forceinline__ float4 apply4(float4 xv, float4 kv) {
    unsigned long long xp0 = pack2(xv.x, xv.y), xp1 = pack2(xv.z, xv.w);
    unsigned long long kp0 = pack2(kv.x, kv.y), kp1 = pack2(kv.z, kv.w);

    unsigned long long vp0 = mul2(xp0, kp0);           // v = x*k
    unsigned long long vp1 = mul2(xp1, kp1);
    unsigned long long v50p0 = mul2(vp0, P50);         // 50*v
    unsigned long long v50p1 = mul2(vp1, P50);
    unsigned long long rp0 = add2(add2(vp0, CP), CN);  // rint(v), RNE magic
    unsigned long long rp1 = add2(add2(vp1, CP), CN);

    float r0, r1, r2, r3, a0, a1, a2, a3;
    unpack2(rp0, r0, r1); unpack2(rp1, r2, r3);
    unpack2(v50p0, a0, a1); unpack2(v50p1, a2, a3);

    float4 o;
    o.x = finish(r0, a0);
    o.y = finish(r1, a1);
    o.z = finish(r2, a2);
    o.w = finish(r3, a3);
    return o;
}

__global__ void __launch_bounds__(TPB, 4)
quan_kernel(const float4* __restrict__ x4,
            const float4* __restrict__ k4,   // kernel = 3 float4s (12 floats)
            float4* __restrict__ o4,
            int n4) {
    int base = blockIdx.x * (TPB * UNROLL) + threadIdx.x;

    // L2 policies: keep most of x resident (0.75 = proven optimum);
    // stream the output through.
    unsigned long long pol_keep, pol_stream;
    asm("createpolicy.fractional.L2::evict_last.b64 %0, 0.75;"  : "=l"(pol_keep));
    asm("createpolicy.fractional.L2::evict_first.b64 %0, 1.0;"  : "=l"(pol_stream));

    // ---- batched, fully coalesced loads (MLP_p1 = UNROLL) ----
    float4 xv[UNROLL];
    bool   ok[UNROLL];
#pragma unroll
    for (int j = 0; j < UNROLL; j++) {
        int idx = base + j * TPB;
        ok[j] = (idx < n4);
        if (ok[j]) xv[j] = ldg_keep(&x4[idx], pol_keep);
    }

    // Compiler barrier: keep all UNROLL loads issued BEFORE any compute/store
    // (protects MLP_p1; R4/R9 showed ptxas otherwise serializes the batch).
    asm volatile("" ::: "memory");

    // kernel-slot rotation once per thread: float4 idx -> slot idx%3,
    // lane stride TPB=256 == 1 (mod 3); 6 iters cycle slots exactly twice.
    float4 k0 = k4[0], k1 = k4[1], k2 = k4[2];
    int s0 = base % 3;
    float4 ka = (s0 == 0) ? k0 : ((s0 == 1) ? k1 : k2);
    float4 kb = (s0 == 0) ? k1 : ((s0 == 1) ? k2 : k0);
    float4 kc = (s0 == 0) ? k2 : ((s0 == 1) ? k0 : k1);

#pragma unroll
    for (int j = 0; j < UNROLL; j++) {
        float4 kv = (j % 3 == 0) ? ka : ((j % 3 == 1) ? kb : kc);
        int idx = base + j * TPB;
        if (ok[j]) {
            float4 ov = apply4(xv[j], kv);
            stg_stream(&o4[idx], ov, pol_stream);
        }
    }
}

extern "C" void kernel_launch(void* const* d_in, const int* in_sizes, int n_in,
                              void* d_out, int out_size) {
    const float* x = (const float*)d_in[0];
    const float* k = (const float*)d_in[1];
    int nx = in_sizes[0];
    if (n_in > 1 && in_sizes[0] < in_sizes[1]) {  // defensive: swapped order
        x = (const float*)d_in[1];
        k = (const float*)d_in[0];
        nx = in_sizes[1];
    }

    int n4 = nx / 4;                               // 6291456
    int per_block = TPB * UNROLL;                  // 1536 float4s/block
    int blocks = (n4 + per_block - 1) / per_block; // 4096
    quan_kernel<<<blocks, TPB>>>((const float4*)x, (const float4*)k,
                                 (float4*)d_out, n4);
}

// round 11
// speedup vs baseline: 1.0009x; 1.0009x over previous
#include <cuda_runtime.h>
#include <cuda_bf16.h>
#include <stdint.h>

// my_ceil(x) = sum_{k=1..150} sigmoid(100*(x-k)) + sigmoid(100*(x+k)) - 150
//
// R=100 => every term with |x-offset| >= 0.5 saturates EXACTLY in fp32; at
// most one term (offset rint(v), if in [-150,150]\{0}) is live. Ungated
// closed form (verified R3-R10, rel_err ~1.2e-7):
//
//   rc = clamp(rint(v), -150, 150)
//   f  = rc + min(|rc|,0.5) * (tanh(50*(v-rc)) - copysign(1, rc))
//
// R11: R7 operating point (proven optimum: batched UNROLL=4 loads + barrier,
// evict_last 0.75 on x, evict_first stores, NO reg squeeze) with TPB=192:
//  - 7 CTAs/SM at regs~48 -> 1344 resident threads (vs 1280 @ TPB=256)
//  - lane stride 192 == 0 (mod 3) AND block stride 768 == 0 (mod 3), so the
//    kernel float4 slot is ONE constant per thread: slot = (base%3). The
//    ka/kb/kc rotation logic disappears entirely.
// DRAM floor analysis: traffic floor ~142MB (201MB - 60MB L2 carve), mixed
// R/W stream ceiling ~5.5TB/s -> ~25.7us kernel floor; R7 is already there.

#define TPB 192
#define UNROLL 4

// ---- packed f32x2 helpers (sm_103a) ----
__device__ __forceinline__ unsigned long long pack2(float a, float b) {
    unsigned long long r;
    asm("mov.b64 %0, {%1,%2};" : "=l"(r) : "f"(a), "f"(b));
    return r;
}
__device__ __forceinline__ void unpack2(unsigned long long p, float& a, float& b) {
    asm("mov.b64 {%0,%1}, %2;" : "=f"(a), "=f"(b) : "l"(p));
}
__device__ __forceinline__ unsigned long long mul2(unsigned long long a, unsigned long long b) {
    unsigned long long r; asm("mul.rn.f32x2 %0, %1, %2;" : "=l"(r) : "l"(a), "l"(b)); return r;
}
__device__ __forceinline__ unsigned long long add2(unsigned long long a, unsigned long long b) {
    unsigned long long r; asm("add.rn.f32x2 %0, %1, %2;" : "=l"(r) : "l"(a), "l"(b)); return r;
}
__device__ __forceinline__ float tanh_fast(float x) {
    float r; asm("tanh.approx.f32 %0, %1;" : "=f"(r) : "f"(x)); return r;
}

// L2 eviction-policy loads/stores
__device__ __forceinline__ float4 ldg_keep(const float4* p, unsigned long long pol) {
    float4 v;
    asm volatile("ld.global.nc.L2::cache_hint.v4.f32 {%0,%1,%2,%3}, [%4], %5;"
                 : "=f"(v.x), "=f"(v.y), "=f"(v.z), "=f"(v.w)
                 : "l"(p), "l"(pol));
    return v;
}
__device__ __forceinline__ void stg_stream(float4* p, float4 v, unsigned long long pol) {
    asm volatile("st.global.L2::cache_hint.v4.f32 [%0], {%1,%2,%3,%4}, %5;"
                 :: "l"(p), "f"(v.x), "f"(v.y), "f"(v.z), "f"(v.w), "l"(pol)
                 : "memory");
}

#define CP   0x4B4000004B400000ull  //  12582912.0f (2^23+2^22, RNE magic)
#define CN   0xCB400000CB400000ull  // -12582912.0f
#define P50  0x4248000042480000ull  //  50.0f packed

__device__ __forceinline__ float finish(float r0, float v50) {
    float rc   = fminf(fmaxf(r0, -150.0f), 150.0f);               // 2x FMNMX
    float w    = fmaf(rc, -50.0f, v50);                           // FFMA
    float th   = tanh_fast(w);                                    // MUFU.TANH
    float smag = fminf(fabsf(rc), 0.5f);                          // FMNMX |src|
    float c1   = __uint_as_float(
        (__float_as_uint(rc) & 0x80000000u) | 0x3F800000u);       // LOP3
    return fmaf(smag, th - c1, rc);                               // FADD + FFMA
}

__device__ __forceinline__ float4 apply4(float4 xv, float4 kv) {
    unsigned long long xp0 = pack2(xv.x, xv.y), xp1 = pack2(xv.z, xv.w);
    unsigned long long kp0 = pack2(kv.x, kv.y), kp1 = pack2(kv.z, kv.w);

    unsigned long long vp0 = mul2(xp0, kp0);           // v = x*k
    unsigned long long vp1 = mul2(xp1, kp1);
    unsigned long long v50p0 = mul2(vp0, P50);         // 50*v
    unsigned long long v50p1 = mul2(vp1, P50);
    unsigned long long rp0 = add2(add2(vp0, CP), CN);  // rint(v), RNE magic
    unsigned long long rp1 = add2(add2(vp1, CP), CN);

    float r0, r1, r2, r3, a0, a1, a2, a3;
    unpack2(rp0, r0, r1); unpack2(rp1, r2, r3);
    unpack2(v50p0, a0, a1); unpack2(v50p1, a2, a3);

    float4 o;
    o.x = finish(r0, a0);
    o.y = finish(r1, a1);
    o.z = finish(r2, a2);
    o.w = finish(r3, a3);
    return o;
}

__global__ void __launch_bounds__(TPB)
quan_kernel(const float4* __restrict__ x4,
            const float4* __restrict__ k4,   // kernel = 3 float4s (12 floats)
            float4* __restrict__ o4,
            int n4) {
    int base = blockIdx.x * (TPB * UNROLL) + threadIdx.x;

    // L2 policies: keep most of x resident (0.75 = proven optimum);
    // stream the output through.
    unsigned long long pol_keep, pol_stream;
    asm("createpolicy.fractional.L2::evict_last.b64 %0, 0.75;"  : "=l"(pol_keep));
    asm("createpolicy.fractional.L2::evict_first.b64 %0, 1.0;"  : "=l"(pol_stream));

    // ---- batched, fully coalesced loads (MLP_p1 = UNROLL) ----
    float4 xv[UNROLL];
    bool   ok[UNROLL];
#pragma unroll
    for (int j = 0; j < UNROLL; j++) {
        int idx = base + j * TPB;
        ok[j] = (idx < n4);
        if (ok[j]) xv[j] = ldg_keep(&x4[idx], pol_keep);
    }

    // Compiler barrier: keep all UNROLL loads issued BEFORE any compute/store
    // (protects MLP_p1; R4/R9 showed ptxas otherwise serializes the batch).
    asm volatile("" ::: "memory");

    // Kernel slot: float4 idx -> slot idx%3. Both the block stride (768) and
    // the lane stride (192) are multiples of 3, so slot = base%3 is ONE
    // constant for all UNROLL iterations of this thread.
    float4 k0 = k4[0], k1 = k4[1], k2 = k4[2];
    int s0 = base % 3;
    float4 kv = (s0 == 0) ? k0 : ((s0 == 1) ? k1 : k2);

#pragma unroll
    for (int j = 0; j < UNROLL; j++) {
        int idx = base + j * TPB;
        if (ok[j]) {
            float4 ov = apply4(xv[j], kv);
            stg_stream(&o4[idx], ov, pol_stream);
        }
    }
}

extern "C" void kernel_launch(void* const* d_in, const int* in_sizes, int n_in,
                              void* d_out, int out_size) {
    const float* x = (const float*)d_in[0];
    const float* k = (const float*)d_in[1];
    int nx = in_sizes[0];
    if (n_in > 1 && in_sizes[0] < in_sizes[1]) {  // defensive: swapped order
        x = (const float*)d_in[1];
        k = (const float*)d_in[0];
        nx = in_sizes[1];
    }

    int n4 = nx / 4;                               // 6291456
    int per_block = TPB * UNROLL;                  // 768 float4s/block
    int blocks = (n4 + per_block - 1) / per_block; // 8192 exact
    quan_kernel<<<blocks, TPB>>>((const float4*)x, (const float4*)k,
                                 (float4*)d_out, n4);
}